// round 8
// baseline (speedup 1.0000x reference)
#include <cuda_runtime.h>
#include <cstdint>
#include <cstddef>

// Butterfly transform: B=8192 rows, N=4096, 12 stages, increasing stride.
// R8 = R2 (best, 86.5us) + overhead trims:
//  - persistent grid (148 CTAs) removes ~3.6 wave transitions at 192KB smem
//  - single code path (branch-free row clamp for the tail tile; clamped pairs
//    duplicate the last valid pair -> identical twiddles/inputs -> benign
//    identical stores)
//  - pair loops at unroll 2 (R4 showed 2-pair ILP == full unroll) to shrink
//    the hot loop from ~90KB to ~15KB of SASS (I$ L1.5-resident)
// Core structure unchanged: 512 threads, 12 rows (6 float2-packed pairs),
// 4 register phases of 3 stages, 3 smem exchanges, conflict-free swizzle,
// 48-reg twiddle cache reused across pairs.

namespace {
constexpr int kN       = 4096;
constexpr int kBatch   = 8192;
constexpr int kThreads = 512;
constexpr int kRows    = 12;
constexpr int kPairs   = kRows / 2;                         // 6
constexpr int kTiles   = 683;
constexpr int kGrid    = 148;                               // persistent
constexpr int kSmem    = kPairs * kN * (int)sizeof(float2); // 196608 B
}

// float2-granule swizzle; conflict-free for i = base + s*m, s in {1,8,64,512}
// (verified per half-warp for all four phase ownerships).
__device__ __forceinline__ int swz(int i) {
    return (i & ~15) | ((i & 15) ^ ((i >> 4) & 7) ^ ((i >> 3) & 8));
}

// One 2x2 butterfly applied to two rows packed in float2 lanes.
__device__ __forceinline__ void bfly(float2& x0, float2& x1, const float4 tm) {
    float2 y0, y1;
    y0.x = __fmaf_rn(tm.y, x1.x, tm.x * x0.x);
    y0.y = __fmaf_rn(tm.y, x1.y, tm.x * x0.y);
    y1.x = __fmaf_rn(tm.w, x1.x, tm.z * x0.x);
    y1.y = __fmaf_rn(tm.w, x1.y, tm.z * x0.y);
    x0 = y0;
    x1 = y1;
}

// Three in-register substages over 8 owned elements (local strides 1,2,4).
__device__ __forceinline__ void substages(float2 v[8], const float4 twr[3][4]) {
    bfly(v[0], v[1], twr[0][0]); bfly(v[2], v[3], twr[0][1]);
    bfly(v[4], v[5], twr[0][2]); bfly(v[6], v[7], twr[0][3]);
    bfly(v[0], v[2], twr[1][0]); bfly(v[1], v[3], twr[1][1]);
    bfly(v[4], v[6], twr[1][2]); bfly(v[5], v[7], twr[1][3]);
    bfly(v[0], v[4], twr[2][0]); bfly(v[1], v[5], twr[2][1]);
    bfly(v[2], v[6], twr[2][2]); bfly(v[3], v[7], twr[2][3]);
}

__global__ void __launch_bounds__(kThreads, 1)
butterfly_kernel(const float* __restrict__ x,
                 const float* __restrict__ tw,
                 float* __restrict__ out) {
    extern __shared__ float2 buf[];
    const int t = threadIdx.x;
    const float4* tw4 = reinterpret_cast<const float4*>(tw);

    // ---- Twiddle register caches for all 4 phases (persistent across tiles)
    float4 tw0[3][4], tw1[3][4], tw2[3][4], tw3[3][4];
    {
        #pragma unroll
        for (int u = 0; u < 3; ++u)
            #pragma unroll
            for (int pm = 0; pm < 4; ++pm)
                tw0[u][pm] = tw4[u * 2048 + 4 * t + pm];
    }
    {
        const int b = t >> 3, c = t & 7;                       // s = 8
        #pragma unroll
        for (int u = 0; u < 3; ++u)
            #pragma unroll
            for (int pm = 0; pm < 4; ++pm)
                tw1[u][pm] = tw4[(3 + u) * 2048 + 8 * (4 * b + pm) + c];
    }
    {
        const int b = t >> 6, c = t & 63;                      // s = 64
        #pragma unroll
        for (int u = 0; u < 3; ++u)
            #pragma unroll
            for (int pm = 0; pm < 4; ++pm)
                tw2[u][pm] = tw4[(6 + u) * 2048 + 64 * (4 * b + pm) + c];
    }
    {
        #pragma unroll
        for (int u = 0; u < 3; ++u)                            // s = 512
            #pragma unroll
            for (int pm = 0; pm < 4; ++pm)
                tw3[u][pm] = tw4[(9 + u) * 2048 + 512 * pm + t];
    }

    // Precomputed smem offsets (bytes of index arithmetic hoisted out of loops)
    int off0[8], off1[8], off2[8], off3[8];
    {
        const int b1 = t >> 3, c1 = t & 7;
        const int b2 = t >> 6, c2 = t & 63;
        #pragma unroll
        for (int m = 0; m < 8; ++m) {
            off0[m] = swz(8 * t + m);
            off1[m] = swz(b1 * 64 + c1 + 8 * m);
            off2[m] = swz(b2 * 512 + c2 + 64 * m);
            off3[m] = swz(t + 512 * m);
        }
    }

    for (int tile = blockIdx.x; tile < kTiles; tile += kGrid) {
        const int row0 = tile * kRows;

        // -------- Phase 0: stages 0..2 (strides 1,2,4), gmem -> smem -------
        #pragma unroll 2
        for (int p = 0; p < kPairs; ++p) {
            const int rA = min(row0 + 2 * p, kBatch - 2);   // branch-free tail
            const float4* xa = reinterpret_cast<const float4*>(x + (size_t)rA * kN);
            const float4* xb = reinterpret_cast<const float4*>(x + (size_t)(rA + 1) * kN);
            const float4 a0 = xa[2 * t], a1 = xa[2 * t + 1];
            const float4 b0 = xb[2 * t], b1 = xb[2 * t + 1];
            float2 v[8];
            v[0] = make_float2(a0.x, b0.x); v[1] = make_float2(a0.y, b0.y);
            v[2] = make_float2(a0.z, b0.z); v[3] = make_float2(a0.w, b0.w);
            v[4] = make_float2(a1.x, b1.x); v[5] = make_float2(a1.y, b1.y);
            v[6] = make_float2(a1.z, b1.z); v[7] = make_float2(a1.w, b1.w);

            substages(v, tw0);

            float2* B = buf + p * kN;
            #pragma unroll
            for (int m = 0; m < 8; ++m) B[off0[m]] = v[m];
        }
        __syncthreads();

        // -------- Phase 1: stages 3..5 (strides 8,16,32), in-place ---------
        #pragma unroll 2
        for (int p = 0; p < kPairs; ++p) {
            float2* B = buf + p * kN;
            float2 v[8];
            #pragma unroll
            for (int m = 0; m < 8; ++m) v[m] = B[off1[m]];
            substages(v, tw1);
            #pragma unroll
            for (int m = 0; m < 8; ++m) B[off1[m]] = v[m];
        }
        __syncthreads();

        // -------- Phase 2: stages 6..8 (strides 64,128,256), in-place ------
        #pragma unroll 2
        for (int p = 0; p < kPairs; ++p) {
            float2* B = buf + p * kN;
            float2 v[8];
            #pragma unroll
            for (int m = 0; m < 8; ++m) v[m] = B[off2[m]];
            substages(v, tw2);
            #pragma unroll
            for (int m = 0; m < 8; ++m) B[off2[m]] = v[m];
        }
        __syncthreads();

        // -------- Phase 3: stages 9..11 (strides 512..2048) -> gmem --------
        #pragma unroll 2
        for (int p = 0; p < kPairs; ++p) {
            float2* B = buf + p * kN;
            float2 v[8];
            #pragma unroll
            for (int m = 0; m < 8; ++m) v[m] = B[off3[m]];
            substages(v, tw3);

            const int rA = min(row0 + 2 * p, kBatch - 2);
            float* oa = out + (size_t)rA * kN;       // clamped dups write
            float* ob = oa + kN;                     // identical values: benign
            #pragma unroll
            for (int m = 0; m < 8; ++m) {
                oa[t + 512 * m] = v[m].x;            // warp-contiguous stores
                ob[t + 512 * m] = v[m].y;
            }
        }
        __syncthreads();   // protect smem reuse by next tile's phase 0
    }
}

extern "C" void kernel_launch(void* const* d_in, const int* in_sizes, int n_in,
                              void* d_out, int out_size) {
    const float* x  = (const float*)d_in[0];   // (8192, 4096) fp32
    const float* tw = (const float*)d_in[1];   // (1,1,12,2048,2,2) fp32
    float* out      = (float*)d_out;           // (8192, 4096) fp32

    cudaFuncSetAttribute(butterfly_kernel,
                         cudaFuncAttributeMaxDynamicSharedMemorySize, kSmem);
    butterfly_kernel<<<kGrid, kThreads, kSmem>>>(x, tw, out);
}

// round 9
// speedup vs baseline: 2.7642x; 2.7642x over previous
#include <cuda_runtime.h>
#include <cstdint>
#include <cstddef>

// Butterfly transform: B=8192 rows, N=4096, 12 stages, increasing stride.
// R9 = R2 structure with QUAD row packing: element = float4 holding the same
// column of 4 rows. Tile = 12 rows = 3 quads, 192KB smem, 512 threads,
// 4 register phases of 3 stages, 3 smem exchanges, phase-scoped 48-reg
// twiddle cache (R8 post-mortem: never hold >1 phase's cache).
// Same bytes through smem but HALF the LDS/STS instructions (.128 vs .64)
// and 2x smaller unrolled code. Swizzle sigma(i) = i ^ ((i>>3)&7) verified
// conflict-free per 8-lane group for patterns i = base + s*m, s in
// {1,8,64,512}, read and write sides.

namespace {
constexpr int kN       = 4096;
constexpr int kBatch   = 8192;
constexpr int kThreads = 512;
constexpr int kRows    = 12;
constexpr int kQuads   = kRows / 4;                         // 3
constexpr int kGrid    = 683;                               // 682 full + 1 tail (2 quads)
constexpr int kSmem    = kQuads * kN * (int)sizeof(float4); // 196608 B
}

// float4-granule swizzle: XOR low-3 index bits with bits 3..5.
__device__ __forceinline__ int swz(int i) { return i ^ ((i >> 3) & 7); }

// One 2x2 butterfly applied to four rows packed in float4 lanes.
__device__ __forceinline__ void bfly(float4& x0, float4& x1, const float4 tm) {
    float4 y0, y1;
    y0.x = __fmaf_rn(tm.y, x1.x, tm.x * x0.x);
    y0.y = __fmaf_rn(tm.y, x1.y, tm.x * x0.y);
    y0.z = __fmaf_rn(tm.y, x1.z, tm.x * x0.z);
    y0.w = __fmaf_rn(tm.y, x1.w, tm.x * x0.w);
    y1.x = __fmaf_rn(tm.w, x1.x, tm.z * x0.x);
    y1.y = __fmaf_rn(tm.w, x1.y, tm.z * x0.y);
    y1.z = __fmaf_rn(tm.w, x1.z, tm.z * x0.z);
    y1.w = __fmaf_rn(tm.w, x1.w, tm.z * x0.w);
    x0 = y0;
    x1 = y1;
}

// Three in-register substages over 8 owned elements (local strides 1,2,4).
__device__ __forceinline__ void substages(float4 v[8], const float4 twr[3][4]) {
    bfly(v[0], v[1], twr[0][0]); bfly(v[2], v[3], twr[0][1]);
    bfly(v[4], v[5], twr[0][2]); bfly(v[6], v[7], twr[0][3]);
    bfly(v[0], v[2], twr[1][0]); bfly(v[1], v[3], twr[1][1]);
    bfly(v[4], v[6], twr[1][2]); bfly(v[5], v[7], twr[1][3]);
    bfly(v[0], v[4], twr[2][0]); bfly(v[1], v[5], twr[2][1]);
    bfly(v[2], v[6], twr[2][2]); bfly(v[3], v[7], twr[2][3]);
}

template <int NQ>
__device__ __forceinline__ void bf_body(const float* __restrict__ x,
                                        const float* __restrict__ tw,
                                        float* __restrict__ out,
                                        int row0, float4* buf) {
    const int t = threadIdx.x;
    const float4* tw4 = reinterpret_cast<const float4*>(tw);

    // ---------------- Phase 0: stages 0..2 (strides 1,2,4) ----------------
    {
        float4 twr[3][4];
        #pragma unroll
        for (int u = 0; u < 3; ++u)
            #pragma unroll
            for (int pm = 0; pm < 4; ++pm)
                twr[u][pm] = tw4[u * 2048 + 4 * t + pm];
        int off[8];
        #pragma unroll
        for (int m = 0; m < 8; ++m) off[m] = swz(8 * t + m);

        #pragma unroll
        for (int q = 0; q < NQ; ++q) {
            // Load elements 8t..8t+7 of rows 4q..4q+3 (2 LDG.128 per row).
            float4 r[4][2];
            #pragma unroll
            for (int j = 0; j < 4; ++j) {
                const float4* xr = reinterpret_cast<const float4*>(
                    x + (size_t)(row0 + 4 * q + j) * kN);
                r[j][0] = xr[2 * t];
                r[j][1] = xr[2 * t + 1];
            }
            // Transpose into row-packed float4 elements.
            float4 v[8];
            v[0] = make_float4(r[0][0].x, r[1][0].x, r[2][0].x, r[3][0].x);
            v[1] = make_float4(r[0][0].y, r[1][0].y, r[2][0].y, r[3][0].y);
            v[2] = make_float4(r[0][0].z, r[1][0].z, r[2][0].z, r[3][0].z);
            v[3] = make_float4(r[0][0].w, r[1][0].w, r[2][0].w, r[3][0].w);
            v[4] = make_float4(r[0][1].x, r[1][1].x, r[2][1].x, r[3][1].x);
            v[5] = make_float4(r[0][1].y, r[1][1].y, r[2][1].y, r[3][1].y);
            v[6] = make_float4(r[0][1].z, r[1][1].z, r[2][1].z, r[3][1].z);
            v[7] = make_float4(r[0][1].w, r[1][1].w, r[2][1].w, r[3][1].w);

            substages(v, twr);

            float4* B = buf + q * kN;
            #pragma unroll
            for (int m = 0; m < 8; ++m) B[off[m]] = v[m];
        }
    }
    __syncthreads();

    // ------------- Phases 1,2: stages 3..8 (strides 8..256), smem ---------
    #pragma unroll
    for (int ph = 1; ph <= 2; ++ph) {
        const int ls = 3 * ph;          // 3 or 6
        const int s  = 1 << ls;         // 8 or 64
        const int b  = t >> ls;
        const int c  = t & (s - 1);

        float4 twr[3][4];
        #pragma unroll
        for (int u = 0; u < 3; ++u)
            #pragma unroll
            for (int pm = 0; pm < 4; ++pm)
                twr[u][pm] = tw4[(3 * ph + u) * 2048 + s * (4 * b + pm) + c];
        int off[8];
        #pragma unroll
        for (int m = 0; m < 8; ++m) off[m] = swz(b * 8 * s + c + s * m);

        #pragma unroll
        for (int q = 0; q < NQ; ++q) {
            float4* B = buf + q * kN;
            float4 v[8];
            #pragma unroll
            for (int m = 0; m < 8; ++m) v[m] = B[off[m]];

            substages(v, twr);

            #pragma unroll
            for (int m = 0; m < 8; ++m) B[off[m]] = v[m];
        }
        __syncthreads();
    }

    // ------------- Phase 3: stages 9..11 (strides 512..2048) -> out -------
    {
        const int s = 512;  // b = 0, c = t
        float4 twr[3][4];
        #pragma unroll
        for (int u = 0; u < 3; ++u)
            #pragma unroll
            for (int pm = 0; pm < 4; ++pm)
                twr[u][pm] = tw4[(9 + u) * 2048 + s * pm + t];
        int off[8];
        #pragma unroll
        for (int m = 0; m < 8; ++m) off[m] = swz(t + s * m);

        #pragma unroll
        for (int q = 0; q < NQ; ++q) {
            float4* B = buf + q * kN;
            float4 v[8];
            #pragma unroll
            for (int m = 0; m < 8; ++m) v[m] = B[off[m]];

            substages(v, twr);

            float* o0 = out + (size_t)(row0 + 4 * q) * kN;
            float* o1 = o0 + kN;
            float* o2 = o1 + kN;
            float* o3 = o2 + kN;
            #pragma unroll
            for (int m = 0; m < 8; ++m) {
                o0[t + s * m] = v[m].x;   // warp-contiguous 4B stores
                o1[t + s * m] = v[m].y;
                o2[t + s * m] = v[m].z;
                o3[t + s * m] = v[m].w;
            }
        }
    }
}

__global__ void __launch_bounds__(kThreads, 1)
butterfly_kernel(const float* __restrict__ x,
                 const float* __restrict__ tw,
                 float* __restrict__ out) {
    extern __shared__ float4 buf[];
    const int row0 = blockIdx.x * kRows;
    if (blockIdx.x < kGrid - 1) {
        bf_body<3>(x, tw, out, row0, buf);   // rows 0..8183
    } else {
        bf_body<2>(x, tw, out, row0, buf);   // rows 8184..8191
    }
}

extern "C" void kernel_launch(void* const* d_in, const int* in_sizes, int n_in,
                              void* d_out, int out_size) {
    const float* x  = (const float*)d_in[0];   // (8192, 4096) fp32
    const float* tw = (const float*)d_in[1];   // (1,1,12,2048,2,2) fp32
    float* out      = (float*)d_out;           // (8192, 4096) fp32

    cudaFuncSetAttribute(butterfly_kernel,
                         cudaFuncAttributeMaxDynamicSharedMemorySize, kSmem);
    butterfly_kernel<<<kGrid, kThreads, kSmem>>>(x, tw, out);
}

// round 10
// speedup vs baseline: 2.8458x; 1.0295x over previous
#include <cuda_runtime.h>
#include <cstdint>
#include <cstddef>

// Butterfly transform: B=8192 rows, N=4096, 12 stages, increasing stride.
// R10 = R9 (quad row packing, tied-best 86.9us) + inter-tile overlap:
//  - persistent grid (148 CTAs), each CTA walks tiles bid, bid+148, ...
//  - during phase 1, prefetch.global.L2 the NEXT tile's 192KB so the
//    DRAM->L2 transfer overlaps phases 1-3 compute; next phase 0 then hits
//    L2 (234 cyc) instead of cold DRAM (577+queue). 28MB/wave fits L2.
//  - __ldg on row loads, one end-of-tile barrier for smem slot reuse.
// Twiddle caches stay PHASE-SCOPED (R8 lesson: never hold all 4 phases).
// Core structure unchanged: 512 threads, 12 rows = 3 float4-packed quads,
// 192KB smem, 4 register phases of 3 stages, 3 smem exchanges,
// conflict-free swizzle sigma(i) = i ^ ((i>>3)&7).

namespace {
constexpr int kN       = 4096;
constexpr int kBatch   = 8192;
constexpr int kThreads = 512;
constexpr int kRows    = 12;
constexpr int kTiles   = 683;                               // 682 full + 1 tail (2 quads)
constexpr int kGrid    = 148;                               // persistent, 1 CTA/SM
constexpr int kSmem    = 3 * kN * (int)sizeof(float4);      // 196608 B
}

// float4-granule swizzle: XOR low-3 index bits with bits 3..5.
__device__ __forceinline__ int swz(int i) { return i ^ ((i >> 3) & 7); }

__device__ __forceinline__ void prefetch_l2(const void* p) {
    asm volatile("prefetch.global.L2 [%0];" :: "l"(p));
}

// One 2x2 butterfly applied to four rows packed in float4 lanes.
__device__ __forceinline__ void bfly(float4& x0, float4& x1, const float4 tm) {
    float4 y0, y1;
    y0.x = __fmaf_rn(tm.y, x1.x, tm.x * x0.x);
    y0.y = __fmaf_rn(tm.y, x1.y, tm.x * x0.y);
    y0.z = __fmaf_rn(tm.y, x1.z, tm.x * x0.z);
    y0.w = __fmaf_rn(tm.y, x1.w, tm.x * x0.w);
    y1.x = __fmaf_rn(tm.w, x1.x, tm.z * x0.x);
    y1.y = __fmaf_rn(tm.w, x1.y, tm.z * x0.y);
    y1.z = __fmaf_rn(tm.w, x1.z, tm.z * x0.z);
    y1.w = __fmaf_rn(tm.w, x1.w, tm.z * x0.w);
    x0 = y0;
    x1 = y1;
}

// Three in-register substages over 8 owned elements (local strides 1,2,4).
__device__ __forceinline__ void substages(float4 v[8], const float4 twr[3][4]) {
    bfly(v[0], v[1], twr[0][0]); bfly(v[2], v[3], twr[0][1]);
    bfly(v[4], v[5], twr[0][2]); bfly(v[6], v[7], twr[0][3]);
    bfly(v[0], v[2], twr[1][0]); bfly(v[1], v[3], twr[1][1]);
    bfly(v[4], v[6], twr[1][2]); bfly(v[5], v[7], twr[1][3]);
    bfly(v[0], v[4], twr[2][0]); bfly(v[1], v[5], twr[2][1]);
    bfly(v[2], v[6], twr[2][2]); bfly(v[3], v[7], twr[2][3]);
}

template <int NQ>
__device__ __forceinline__ void bf_body(const float* __restrict__ x,
                                        const float* __restrict__ tw,
                                        float* __restrict__ out,
                                        int row0, int nrow0, float4* buf) {
    const int t = threadIdx.x;
    const float4* tw4 = reinterpret_cast<const float4*>(tw);

    // ---------------- Phase 0: stages 0..2 (strides 1,2,4) ----------------
    {
        float4 twr[3][4];
        #pragma unroll
        for (int u = 0; u < 3; ++u)
            #pragma unroll
            for (int pm = 0; pm < 4; ++pm)
                twr[u][pm] = tw4[u * 2048 + 4 * t + pm];
        int off[8];
        #pragma unroll
        for (int m = 0; m < 8; ++m) off[m] = swz(8 * t + m);

        #pragma unroll
        for (int q = 0; q < NQ; ++q) {
            // Load elements 8t..8t+7 of rows 4q..4q+3 (2 LDG.128 per row).
            float4 r[4][2];
            #pragma unroll
            for (int j = 0; j < 4; ++j) {
                const float4* xr = reinterpret_cast<const float4*>(
                    x + (size_t)(row0 + 4 * q + j) * kN);
                r[j][0] = __ldg(xr + 2 * t);
                r[j][1] = __ldg(xr + 2 * t + 1);
            }
            // Transpose into row-packed float4 elements.
            float4 v[8];
            v[0] = make_float4(r[0][0].x, r[1][0].x, r[2][0].x, r[3][0].x);
            v[1] = make_float4(r[0][0].y, r[1][0].y, r[2][0].y, r[3][0].y);
            v[2] = make_float4(r[0][0].z, r[1][0].z, r[2][0].z, r[3][0].z);
            v[3] = make_float4(r[0][0].w, r[1][0].w, r[2][0].w, r[3][0].w);
            v[4] = make_float4(r[0][1].x, r[1][1].x, r[2][1].x, r[3][1].x);
            v[5] = make_float4(r[0][1].y, r[1][1].y, r[2][1].y, r[3][1].y);
            v[6] = make_float4(r[0][1].z, r[1][1].z, r[2][1].z, r[3][1].z);
            v[7] = make_float4(r[0][1].w, r[1][1].w, r[2][1].w, r[3][1].w);

            substages(v, twr);

            float4* B = buf + q * kN;
            #pragma unroll
            for (int m = 0; m < 8; ++m) B[off[m]] = v[m];
        }
    }
    __syncthreads();

    // ------------- Phases 1,2: stages 3..8 (strides 8..256), smem ---------
    #pragma unroll
    for (int ph = 1; ph <= 2; ++ph) {
        const int ls = 3 * ph;          // 3 or 6
        const int s  = 1 << ls;         // 8 or 64
        const int b  = t >> ls;
        const int c  = t & (s - 1);

        float4 twr[3][4];
        #pragma unroll
        for (int u = 0; u < 3; ++u)
            #pragma unroll
            for (int pm = 0; pm < 4; ++pm)
                twr[u][pm] = tw4[(3 * ph + u) * 2048 + s * (4 * b + pm) + c];
        int off[8];
        #pragma unroll
        for (int m = 0; m < 8; ++m) off[m] = swz(b * 8 * s + c + s * m);

        // Prefetch the NEXT tile's 192KB into L2 while phases 1-3 compute.
        if (ph == 1 && nrow0 >= 0) {
            const char* nb = reinterpret_cast<const char*>(
                x + (size_t)nrow0 * kN);
            #pragma unroll
            for (int k = 0; k < 3; ++k)
                prefetch_l2(nb + (size_t)(t + 512 * k) * 128);
        }

        #pragma unroll
        for (int q = 0; q < NQ; ++q) {
            float4* B = buf + q * kN;
            float4 v[8];
            #pragma unroll
            for (int m = 0; m < 8; ++m) v[m] = B[off[m]];

            substages(v, twr);

            #pragma unroll
            for (int m = 0; m < 8; ++m) B[off[m]] = v[m];
        }
        __syncthreads();
    }

    // ------------- Phase 3: stages 9..11 (strides 512..2048) -> out -------
    {
        const int s = 512;  // b = 0, c = t
        float4 twr[3][4];
        #pragma unroll
        for (int u = 0; u < 3; ++u)
            #pragma unroll
            for (int pm = 0; pm < 4; ++pm)
                twr[u][pm] = tw4[(9 + u) * 2048 + s * pm + t];
        int off[8];
        #pragma unroll
        for (int m = 0; m < 8; ++m) off[m] = swz(t + s * m);

        #pragma unroll
        for (int q = 0; q < NQ; ++q) {
            float4* B = buf + q * kN;
            float4 v[8];
            #pragma unroll
            for (int m = 0; m < 8; ++m) v[m] = B[off[m]];

            substages(v, twr);

            float* o0 = out + (size_t)(row0 + 4 * q) * kN;
            float* o1 = o0 + kN;
            float* o2 = o1 + kN;
            float* o3 = o2 + kN;
            #pragma unroll
            for (int m = 0; m < 8; ++m) {
                o0[t + s * m] = v[m].x;   // warp-contiguous 4B stores
                o1[t + s * m] = v[m].y;
                o2[t + s * m] = v[m].z;
                o3[t + s * m] = v[m].w;
            }
        }
    }
    __syncthreads();   // slots reused by next tile's phase 0
}

__global__ void __launch_bounds__(kThreads, 1)
butterfly_kernel(const float* __restrict__ x,
                 const float* __restrict__ tw,
                 float* __restrict__ out) {
    extern __shared__ float4 buf[];

    for (int tile = blockIdx.x; tile < kTiles; tile += kGrid) {
        const int row0  = tile * kRows;
        const int nt    = tile + kGrid;
        const int nrow0 = (nt < kTiles) ? nt * kRows : -1;

        if (tile != kTiles - 1) {
            bf_body<3>(x, tw, out, row0, nrow0, buf);   // 12-row tiles
        } else {
            bf_body<2>(x, tw, out, row0, nrow0, buf);   // tail: rows 8184..8191
        }
    }
}

extern "C" void kernel_launch(void* const* d_in, const int* in_sizes, int n_in,
                              void* d_out, int out_size) {
    const float* x  = (const float*)d_in[0];   // (8192, 4096) fp32
    const float* tw = (const float*)d_in[1];   // (1,1,12,2048,2,2) fp32
    float* out      = (float*)d_out;           // (8192, 4096) fp32

    cudaFuncSetAttribute(butterfly_kernel,
                         cudaFuncAttributeMaxDynamicSharedMemorySize, kSmem);
    butterfly_kernel<<<kGrid, kThreads, kSmem>>>(x, tw, out);
}